// round 10
// baseline (speedup 1.0000x reference)
#include <cuda_runtime.h>
#include <cstdint>

#define S 4096
#define MAXLEN 50
#define NATT 64

// ---------------- scratch ----------------
__device__ float g_G[2 * S * 300];
__device__ float g_WTenc[2 * 256 * 300];
__device__ float g_WAT[200 * 400];
__device__ float g_enc[S * 200];
__device__ float g_kp[S * 200];             // kp row-major [i][k]
__device__ float g_vp[S * 200];             // vp row-major [i][g]
__device__ float g_QL[1000 * 200];          // Wq[:,100:200] @ L_tab[i]
__device__ float g_GL[1000 * 300];          // dec_Wih[:,100:200] @ L_tab[i]
__device__ float g_gihd0[300];              // dec_Wih[:,100:200] @ sent  (t=0 path)
__device__ float g_q[200];
__device__ float g_hd[100];
__device__ float g_qpart[200];
__device__ int   g_idx;
__device__ float g_pm[NATT];
__device__ float g_pz[NATT];
__device__ float g_pv[NATT * 200];
__device__ float g_pamv[NATT];
__device__ int   g_pami[NATT];
__device__ unsigned g_cnt1[MAXLEN];
__device__ unsigned g_cnt2[MAXLEN];
__device__ unsigned g_hdflag[MAXLEN];
__device__ unsigned g_qpflag[MAXLEN];
__device__ unsigned g_qflag[MAXLEN + 1];

__device__ __forceinline__ float tanhapx(float x) {
    float y; asm("tanh.approx.f32 %0, %1;" : "=f"(y) : "f"(x)); return y;
}
__device__ __forceinline__ float sigapx(float x) {
    return 0.5f + 0.5f * tanhapx(0.5f * x);
}
__device__ __forceinline__ unsigned vld(const unsigned* p) {
    return *(volatile const unsigned*)p;
}
__device__ __forceinline__ float warp_sum(float a) {
#pragma unroll
    for (int o = 16; o; o >>= 1) a += __shfl_xor_sync(0xffffffffu, a, o);
    return a;
}
__device__ __forceinline__ float warp_max(float a) {
#pragma unroll
    for (int o = 16; o; o >>= 1) a = fmaxf(a, __shfl_xor_sync(0xffffffffu, a, o));
    return a;
}
__device__ __forceinline__ float red8(float a) {
    a += __shfl_xor_sync(0xffffffffu, a, 4);
    a += __shfl_xor_sync(0xffffffffu, a, 2);
    a += __shfl_xor_sync(0xffffffffu, a, 1);
    return a;
}

// ---------------- K_transp ----------------
__global__ void k_transp(const float* fWih, const float* bWih, const float* attW) {
    int region = blockIdx.y;
    const float* src; float* dst; int R, C;
    switch (region) {
        case 0: src = fWih;             dst = g_WTenc;          R = 300; C = 256; break;
        case 1: src = bWih;             dst = g_WTenc + 76800;  R = 300; C = 256; break;
        default: src = attW + 200*200;  dst = g_WAT;            R = 400; C = 200; break;
    }
    int total = R * C;
    for (int idx = blockIdx.x * blockDim.x + threadIdx.x; idx < total;
         idx += gridDim.x * blockDim.x) {
        int r = idx / C, c = idx % C;
        dst[c * R + r] = src[r * C + c];
    }
}

// ---------------- K_tab: QL/GL tables ----------------
__global__ void __launch_bounds__(512) k_tab(const float* attInW, const float* decWih,
                                             const float* L_tab) {
    __shared__ float Lt[16][100];
    int tid = threadIdx.x;
    int ib = blockIdx.x * 16;
    for (int i = tid; i < 16 * 100; i += 512) {
        int j = i / 100, k = i % 100;
        Lt[j][k] = (ib + j < 1000) ? L_tab[(ib + j) * 100 + k] : 0.f;
    }
    __syncthreads();
    if (tid < 500) {
        const float* wp = (tid < 200) ? (attInW + tid * 200 + 100)
                                      : (decWih + (tid - 200) * 400 + 100);
        float acc[16];
#pragma unroll
        for (int j = 0; j < 16; j++) acc[j] = 0.f;
        for (int k = 0; k < 100; k++) {
            float wv = wp[k];
#pragma unroll
            for (int j = 0; j < 16; j++) acc[j] += wv * Lt[j][k];
        }
        for (int j = 0; j < 16; j++) {
            if (ib + j < 1000) {
                if (tid < 200) g_QL[(ib + j) * 200 + tid] = acc[j];
                else           g_GL[(ib + j) * 300 + tid - 200] = acc[j];
            }
        }
    }
}

// ---------------- K0: gi precompute ----------------
__global__ void __launch_bounds__(320) k_gi(const int* x, const float* E_tab,
                                            const float* fbih, const float* fbhh,
                                            const float* bbih, const float* bbhh) {
    int dir = blockIdx.y;
    int t0 = blockIdx.x * 16;
    __shared__ int xi[16];
    __shared__ __align__(16) float emb_s[16 * 256];
    int tid = threadIdx.x;
    if (tid < 16) {
        int tg = dir ? (S - 1 - (t0 + tid)) : (t0 + tid);
        xi[tid] = x[tg];
    }
    __syncthreads();
    for (int i = tid; i < 16 * 256; i += 320) {
        int tt = i >> 8, k = i & 255;
        emb_s[i] = E_tab[(size_t)xi[tt] * 256 + k];
    }
    __syncthreads();
    if (tid < 300) {
        int g = tid;
        const float* bih = dir ? bbih : fbih;
        const float* bhh = dir ? bbhh : fbhh;
        float bias = bih[g] + (g < 200 ? bhh[g] : 0.f);
        float acc[16];
#pragma unroll
        for (int tt = 0; tt < 16; tt++) acc[tt] = bias;
        const float* WT = g_WTenc + dir * 256 * 300;
        for (int k4 = 0; k4 < 64; k4++) {
            float w0 = WT[(4 * k4 + 0) * 300 + g];
            float w1 = WT[(4 * k4 + 1) * 300 + g];
            float w2 = WT[(4 * k4 + 2) * 300 + g];
            float w3 = WT[(4 * k4 + 3) * 300 + g];
#pragma unroll
            for (int tt = 0; tt < 16; tt++) {
                float4 e = *reinterpret_cast<const float4*>(emb_s + tt * 256 + 4 * k4);
                acc[tt] += e.x * w0 + e.y * w1 + e.z * w2 + e.w * w3;
            }
        }
        float* Gd = g_G + (size_t)dir * S * 300;
#pragma unroll
        for (int tt = 0; tt < 16; tt++) Gd[(t0 + tt) * 300 + g] = acc[tt];
    }
}

// ---------------- K1: GRU recurrence, 640 threads, 1 barrier/step ----------------
// 20 warps; lane layout: 6 lanes per output j (gate r/z/n x half c0/c1), 5 outputs
// per warp, lanes 30/31 idle. Half-dots combined by shfl; h double-buffered.
__global__ void __launch_bounds__(640, 1) k_recur(const float* fWhh, const float* bWhh,
                                                  const float* fbhh, const float* bbhh) {
    int dir = blockIdx.x;
    const float* Whh = dir ? bWhh : fWhh;
    const float* bhh = dir ? bbhh : fbhh;
    const float* Gd = g_G + (size_t)dir * S * 300;
    __shared__ __align__(16) float h2[2][128];   // halves at [0..49] and [64..113]
    int tid = threadIdx.x;
    int w = tid >> 5, lane = tid & 31;
    int group = lane / 6, role = lane % 6;
    bool act = (lane < 30);
    int j = w * 5 + group;
    int jw = (act && j < 100) ? j : 99;          // clamped for weight loads
    int gate = role >> 1;                         // 0=r,1=z,2=n
    int c = role & 1;
    int row = gate * 100 + jw;

    unsigned long long wr[25];
    {
        const unsigned long long* wp =
            reinterpret_cast<const unsigned long long*>(Whh + row * 100 + c * 50);
#pragma unroll
        for (int k = 0; k < 25; k++) wr[k] = wp[k];
    }
    bool lead = act && (role == 0);
    float gr = 0.f, gz = 0.f, gn = 0.f, bhn = 0.f, h_reg = 0.f;
    if (lead) {
        gr = Gd[j]; gz = Gd[100 + j]; gn = Gd[200 + j];
        bhn = bhh[200 + j];
    }
    if (tid < 128) { h2[0][tid] = 0.f; h2[1][tid] = 0.f; }
    __syncthreads();

    float* outbase = g_enc + (dir ? 100 : 0);
    int hidx = (j < 50) ? j : j + 14;
    for (int t = 0; t < S; t++) {
        // prefetch G for t+1 (lead lanes only)
        float ngr = 0.f, ngz = 0.f, ngn = 0.f;
        if (lead) {
            int tn = (t + 1 < S) ? (t + 1) : (S - 1);
            const float* Gp = Gd + tn * 300;
            ngr = Gp[j]; ngz = Gp[100 + j]; ngn = Gp[200 + j];
        }
        // half-row dot: 50 floats = 12 ulonglong2 + 1 ulonglong
        const float* hbuf = h2[t & 1] + c * 64;
        const ulonglong2* hp = reinterpret_cast<const ulonglong2*>(hbuf);
        unsigned long long a0 = 0ULL, a1 = 0ULL, a2 = 0ULL, a3 = 0ULL;
#pragma unroll
        for (int i = 0; i < 6; i++) {
            ulonglong2 ha = hp[2 * i];
            ulonglong2 hb = hp[2 * i + 1];
            asm("fma.rn.f32x2 %0, %1, %2, %0;" : "+l"(a0) : "l"(wr[4*i]),   "l"(ha.x));
            asm("fma.rn.f32x2 %0, %1, %2, %0;" : "+l"(a1) : "l"(wr[4*i+1]), "l"(ha.y));
            asm("fma.rn.f32x2 %0, %1, %2, %0;" : "+l"(a2) : "l"(wr[4*i+2]), "l"(hb.x));
            asm("fma.rn.f32x2 %0, %1, %2, %0;" : "+l"(a3) : "l"(wr[4*i+3]), "l"(hb.y));
        }
        {
            unsigned long long hl =
                *reinterpret_cast<const unsigned long long*>(hbuf + 48);
            asm("fma.rn.f32x2 %0, %1, %2, %0;" : "+l"(a0) : "l"(wr[24]), "l"(hl));
        }
        asm("add.rn.f32x2 %0, %0, %1;" : "+l"(a0) : "l"(a2));
        asm("add.rn.f32x2 %0, %0, %1;" : "+l"(a1) : "l"(a3));
        asm("add.rn.f32x2 %0, %0, %1;" : "+l"(a0) : "l"(a1));
        float2 f = *reinterpret_cast<float2*>(&a0);
        float val = f.x + f.y;
        // combine halves: roles 0,2,4 get full gate dots
        float v = val + __shfl_down_sync(0xffffffffu, val, 1);
        float vz = __shfl_down_sync(0xffffffffu, v, 2);
        float vn = __shfl_down_sync(0xffffffffu, v, 4);
        if (lead) {
            float rg = sigapx(gr + v);
            float zg = sigapx(gz + vz);
            float ng = tanhapx(gn + rg * (vn + bhn));
            float hn = ng + zg * (h_reg - ng);
            h_reg = hn;
            h2[(t + 1) & 1][hidx] = hn;
            int trow = dir ? (S - 1 - t) : t;
            outbase[trow * 200 + j] = hn;
            gr = ngr; gz = ngz; gn = ngn;
        }
        __syncthreads();
    }
}

// ---------------- K2: kp and vp (both row-major) ----------------
__global__ void __launch_bounds__(416) k_kv(const float* att_in_b) {
    int i0 = blockIdx.x * 16;
    __shared__ __align__(16) float enc_s[16 * 200];
    int tid = threadIdx.x;
    for (int i = tid; i < 3200; i += 416) enc_s[i] = g_enc[i0 * 200 + i];
    __syncthreads();
    if (tid < 400) {
        int g = tid;
        float bias = att_in_b[200 + g];
        float acc[16];
#pragma unroll
        for (int tt = 0; tt < 16; tt++) acc[tt] = bias;
        for (int k4 = 0; k4 < 50; k4++) {
            float w0 = g_WAT[(4 * k4 + 0) * 400 + g];
            float w1 = g_WAT[(4 * k4 + 1) * 400 + g];
            float w2 = g_WAT[(4 * k4 + 2) * 400 + g];
            float w3 = g_WAT[(4 * k4 + 3) * 400 + g];
#pragma unroll
            for (int tt = 0; tt < 16; tt++) {
                float4 e = *reinterpret_cast<const float4*>(enc_s + tt * 200 + 4 * k4);
                acc[tt] += e.x * w0 + e.y * w1 + e.z * w2 + e.w * w3;
            }
        }
        if (g < 200) {
#pragma unroll
            for (int tt = 0; tt < 16; tt++) g_kp[(i0 + tt) * 200 + g] = acc[tt];
        } else {
            int vg = g - 200;
#pragma unroll
            for (int tt = 0; tt < 16; tt++) g_vp[(i0 + tt) * 200 + vg] = acc[tt];
        }
    }
}

// ---------------- K3: sent, q0, gihd0, flag reset ----------------
__global__ void __launch_bounds__(512) k_sent(const float* mid_W, const float* mid_b,
                                              const float* att_in_W, const float* att_in_b,
                                              const float* decWih) {
    __shared__ float u[200];
    __shared__ float sent_s[100];
    int tid = threadIdx.x;
    for (int i = tid; i < MAXLEN; i += 512) {
        g_cnt1[i] = 0; g_cnt2[i] = 0; g_hdflag[i] = 0; g_qflag[i] = 0; g_qpflag[i] = 0;
    }
    if (tid == 0) g_qflag[MAXLEN] = 0;
    if (tid < 100) {
        u[tid] = g_enc[100 + tid];
        u[100 + tid] = g_enc[(S - 1) * 200 + tid];
    }
    __syncthreads();
    if (tid < 100) {
        float acc = mid_b[tid];
#pragma unroll 4
        for (int k = 0; k < 200; k++) acc += mid_W[tid * 200 + k] * u[k];
        sent_s[tid] = acc;
    }
    __syncthreads();
    if (tid < 200) {
        float acc = att_in_b[tid];
#pragma unroll 4
        for (int k = 0; k < 100; k++) acc += att_in_W[tid * 200 + 100 + k] * sent_s[k];
        g_q[tid] = acc;
    }
    if (tid < 300) {
        float acc = 0.f;
#pragma unroll 4
        for (int k = 0; k < 100; k++) acc += decWih[tid * 400 + 100 + k] * sent_s[k];
        g_gihd0[tid] = acc;
    }
}

// ---------------- fused persistent decoder ----------------
struct SAtt {
    float kp[64 * 200];   // [row][k]
    float vp[64 * 200];   // [i][g]
    float lw[16 * 100];
    float lb[16];
    float q[200];
    float s[64];
    float e[64];
    float hd[100];
    float pvp[4 * 200];
    float scp[16 * 4];
    float sc[16];
    float redM;
    int fin;
    int idxs;
};
struct SEpi {
    float pm[64], pz[64], coef[64];
    float part[4 * 200];
    float araw[200];
    float att_s[200];
    float gi[300];
    float gibias[300];
    float dhn[100];
    float bo[200], bq[200];
    float hd_s[100];
    float ghd_s[300];
    float redM, invZ;
};

__global__ void __launch_bounds__(1024, 1) k_dec(
    const float* attOutW, const float* attOutB,
    const float* decWih, const float* dec_bih, const float* dec_bhh,
    const float* lastB, const float* lastW,
    const float* attInW, const float* attInB, float* out) {
    extern __shared__ char sm_raw[];
    int tid = threadIdx.x;
    int b = blockIdx.x;
    int g8 = tid >> 3, s8 = tid & 7;

    if (b < NATT) {
        // ================= attention / scores block =================
        SAtt* sm = (SAtt*)sm_raw;
        int i0 = b * 64;
        for (int i = tid; i < 12800; i += 1024) sm->kp[i] = g_kp[i0 * 200 + i];
        for (int i = tid; i < 12800; i += 1024) sm->vp[i] = g_vp[i0 * 200 + i];
        int r0 = b * 16;
        int nrows = 1000 - r0; if (nrows > 16) nrows = 16; if (nrows < 0) nrows = 0;
        for (int i = tid; i < nrows * 100; i += 1024) sm->lw[i] = lastW[r0 * 100 + i];
        if (tid < nrows) sm->lb[tid] = lastB[r0 + tid];
        __syncthreads();
        const float SCALE = 0.07071067811865475f;  // 1/sqrt(200)
        int g16 = tid >> 4, s16 = tid & 15;

        for (int t = 0; t < MAXLEN; t++) {
            if (t > 0) {
                if (tid == 0) while (vld(&g_qflag[t]) == 0u) __nanosleep(20);
                __syncthreads();
            }
            if (tid < 200) sm->q[tid] = __ldcg(&g_q[tid]);
            __syncthreads();
            // s = kp @ q : 16 lanes per row
            if (g16 < 64) {
                float acc = 0.f;
#pragma unroll
                for (int jx = 0; jx < 13; jx++) {
                    int k = s16 + 16 * jx;
                    if (k < 200) acc += sm->kp[g16 * 200 + k] * sm->q[k];
                }
                acc += __shfl_xor_sync(0xffffffffu, acc, 8);
                acc = red8(acc);
                if (s16 == 0) sm->s[g16] = acc * SCALE;
            }
            __syncthreads();
            if (tid < 32) {
                float m = warp_max(fmaxf(sm->s[tid], sm->s[tid + 32]));
                if (tid == 0) sm->redM = m;
            }
            __syncthreads();
            if (tid < 64) sm->e[tid] = __expf(sm->s[tid] - sm->redM);
            __syncthreads();
            if (tid < 32) {
                float z = warp_sum(sm->e[tid] + sm->e[tid + 32]);
                if (tid == 0) { __stcg(&g_pm[b], sm->redM); __stcg(&g_pz[b], z); }
            }
            if (tid < 800) {
                int g = tid % 200, ip = tid / 200;
                float a = 0.f;
#pragma unroll
                for (int jx = 0; jx < 16; jx++) {
                    int i2 = ip * 16 + jx;
                    a += sm->e[i2] * sm->vp[i2 * 200 + g];
                }
                sm->pvp[ip * 200 + g] = a;
            }
            __syncthreads();
            if (tid < 200) {
                float a = sm->pvp[tid] + sm->pvp[200 + tid] + sm->pvp[400 + tid] +
                          sm->pvp[600 + tid];
                __stcg(&g_pv[b * 200 + tid], a);
            }
            __threadfence();
            __syncthreads();
            if (tid == 0) atomicAdd(&g_cnt1[t], 1u);

            // wait for hd from epilogue
            if (tid == 0) while (vld(&g_hdflag[t]) == 0u) __nanosleep(20);
            __syncthreads();
            if (tid < 100) sm->hd[tid] = __ldcg(&g_hd[tid]);
            __syncthreads();
            if (tid < nrows * 4) {
                int row = tid >> 2, kp4 = tid & 3;
                float a = 0.f;
#pragma unroll
                for (int kk = 0; kk < 25; kk++)
                    a += sm->lw[row * 100 + kp4 * 25 + kk] * sm->hd[kp4 * 25 + kk];
                sm->scp[tid] = a;
            }
            __syncthreads();
            if (tid < nrows) {
                float sc = sm->scp[tid * 4] + sm->scp[tid * 4 + 1] +
                           sm->scp[tid * 4 + 2] + sm->scp[tid * 4 + 3] + sm->lb[tid];
                sm->sc[tid] = sc;
                out[t * 1000 + r0 + tid] = sc;
            }
            __syncthreads();
            if (tid == 0) {
                float bv = -3.4e38f; int bi = 0x7fffffff;
                for (int rr = 0; rr < nrows; rr++)
                    if (sm->sc[rr] > bv) { bv = sm->sc[rr]; bi = r0 + rr; }
                __stcg(&g_pamv[b], bv);
                __stcg(&g_pami[b], bi);
                __threadfence();
                unsigned old = atomicAdd(&g_cnt2[t], 1u);
                sm->fin = (old == NATT - 1) ? 1 : 0;
            }
            __syncthreads();
            if (sm->fin) {
                // last block: global argmax + q finalize
                if (tid < 32) {
                    float v1 = __ldcg(&g_pamv[tid]), v2 = __ldcg(&g_pamv[tid + 32]);
                    int i1 = __ldcg(&g_pami[tid]), i2 = __ldcg(&g_pami[tid + 32]);
                    float bv; int bi;
                    if (v1 > v2 || (v1 == v2 && i1 < i2)) { bv = v1; bi = i1; }
                    else { bv = v2; bi = i2; }
#pragma unroll
                    for (int o = 16; o; o >>= 1) {
                        float ov = __shfl_xor_sync(0xffffffffu, bv, o);
                        int oi = __shfl_xor_sync(0xffffffffu, bi, o);
                        if (ov > bv || (ov == bv && oi < bi)) { bv = ov; bi = oi; }
                    }
                    if (tid == 0) sm->idxs = bi;
                }
                if (tid == 0) while (vld(&g_qpflag[t]) == 0u) __nanosleep(20);
                __syncthreads();
                int idx = sm->idxs;
                if (tid < 200)
                    __stcg(&g_q[tid], __ldcg(&g_qpart[tid]) + g_QL[idx * 200 + tid]);
                if (tid == 0) *(volatile int*)&g_idx = idx;
                __threadfence();
                __syncthreads();
                if (tid == 0) *(volatile unsigned*)&g_qflag[t + 1] = 1u;
            }
            __syncthreads();
        }
    } else {
        // ================= epilogue block =================
        SEpi* sm = (SEpi*)sm_raw;
        for (int i = tid; i < 300; i += 1024)
            sm->gibias[i] = dec_bih[i] + (i < 200 ? dec_bhh[i] : 0.f);
        for (int i = tid; i < 100; i += 1024) sm->dhn[i] = dec_bhh[200 + i];
        for (int i = tid; i < 200; i += 1024) {
            sm->bo[i] = attOutB[i];
            sm->bq[i] = attInB[i];
        }
        __syncthreads();

        for (int t = 0; t < MAXLEN; t++) {
            if (tid == 0) while (vld(&g_cnt1[t]) < NATT) __nanosleep(20);
            __syncthreads();
            // prefetch GL contribution (idx-dependent) while softmax/attproj run
            float glv = 0.f;
            if (tid < 300) {
                if (t == 0) glv = g_gihd0[tid];
                else {
                    int idx = *(volatile int*)&g_idx;
                    glv = __ldcg(&g_GL[idx * 300 + tid]);
                }
            }
            if (tid < 64) sm->pm[tid] = __ldcg(&g_pm[tid]);
            else if (tid < 128) sm->pz[tid - 64] = __ldcg(&g_pz[tid - 64]);
            __syncthreads();
            if (tid < 32) {
                float m = warp_max(fmaxf(sm->pm[tid], sm->pm[tid + 32]));
                if (tid == 0) sm->redM = m;
            }
            __syncthreads();
            if (tid < 64) sm->coef[tid] = __expf(sm->pm[tid] - sm->redM);
            __syncthreads();
            if (tid < 32) {
                float z = warp_sum(sm->coef[tid] * sm->pz[tid] +
                                   sm->coef[tid + 32] * sm->pz[tid + 32]);
                if (tid == 0) sm->invZ = __fdividef(1.f, z);
            }
            __syncthreads();
            if (tid < 800) {
                int g = tid % 200, ip = tid / 200;
                float a = 0.f;
#pragma unroll
                for (int jx = 0; jx < 16; jx++) {
                    int bb = ip * 16 + jx;
                    a += sm->coef[bb] * __ldcg(&g_pv[bb * 200 + g]);
                }
                sm->part[ip * 200 + g] = a;
            }
            __syncthreads();
            if (tid < 200)
                sm->araw[tid] = (sm->part[tid] + sm->part[200 + tid] +
                                 sm->part[400 + tid] + sm->part[600 + tid]) * sm->invZ;
            __syncthreads();
            // att projection: 8 lanes per row
            for (int r = g8; r < 200; r += 128) {
                float a = 0.f;
#pragma unroll
                for (int jx = 0; jx < 25; jx++) {
                    int k = s8 + 8 * jx;
                    a += attOutW[r * 200 + k] * sm->araw[k];
                }
                a = red8(a);
                if (s8 == 0) sm->att_s[r] = a + sm->bo[r];
            }
            __syncthreads();
            // gi (att part): 8 lanes per row over dec_Wih[:, 200:400]
            for (int r = g8; r < 300; r += 128) {
                float a = 0.f;
#pragma unroll
                for (int jx = 0; jx < 25; jx++) {
                    int k = s8 + 8 * jx;
                    a += decWih[r * 400 + 200 + k] * sm->att_s[k];
                }
                a = red8(a);
                if (s8 == 0) sm->gi[r] = a;
            }
            __syncthreads();
            if (tid < 300) {
                float base = sm->gi[tid] + glv + sm->gibias[tid];
                if (t > 0) base += sm->ghd_s[tid];
                sm->gi[tid] = base;
            }
            __syncthreads();
            if (tid < 100) {
                float r_ = sigapx(sm->gi[tid]);
                float z_ = sigapx(sm->gi[100 + tid]);
                float n_ = tanhapx(sm->gi[200 + tid] + r_ * sm->dhn[tid]);
                float hd = (1.f - z_) * n_;
                sm->hd_s[tid] = hd;
                __stcg(&g_hd[tid], hd);
            }
            __threadfence();
            __syncthreads();
            if (tid == 0) *(volatile unsigned*)&g_hdflag[t] = 1u;

            // overlap with att scores: ghd_pre (next step) + qpart (finalizer)
            for (int rr = g8; rr < 500; rr += 128) {
                float a = 0.f;
                if (rr < 300) {
#pragma unroll
                    for (int jx = 0; jx < 13; jx++) {
                        int k = s8 + 8 * jx;
                        if (k < 100) a += decWih[rr * 400 + k] * sm->hd_s[k];
                    }
                } else {
#pragma unroll
                    for (int jx = 0; jx < 13; jx++) {
                        int k = s8 + 8 * jx;
                        if (k < 100) a += attInW[(rr - 300) * 200 + k] * sm->hd_s[k];
                    }
                }
                a = red8(a);
                if (s8 == 0) {
                    if (rr < 300) sm->ghd_s[rr] = a;
                    else __stcg(&g_qpart[rr - 300], a + sm->bq[rr - 300]);
                }
            }
            __threadfence();
            __syncthreads();
            if (tid == 0) *(volatile unsigned*)&g_qpflag[t] = 1u;
        }
    }
}

// ---------------- host launcher ----------------
extern "C" void kernel_launch(void* const* d_in, const int* in_sizes, int n_in,
                              void* d_out, int out_size) {
    const int*   x         = (const int*)  d_in[0];
    const float* E_tab     = (const float*)d_in[1];
    const float* L_tab     = (const float*)d_in[2];
    const float* enc_f_Wih = (const float*)d_in[3];
    const float* enc_f_Whh = (const float*)d_in[4];
    const float* enc_f_bih = (const float*)d_in[5];
    const float* enc_f_bhh = (const float*)d_in[6];
    const float* enc_b_Wih = (const float*)d_in[7];
    const float* enc_b_Whh = (const float*)d_in[8];
    const float* enc_b_bih = (const float*)d_in[9];
    const float* enc_b_bhh = (const float*)d_in[10];
    const float* mid_W     = (const float*)d_in[11];
    const float* mid_b     = (const float*)d_in[12];
    const float* dec_Wih   = (const float*)d_in[15];
    const float* dec_bih   = (const float*)d_in[17];
    const float* dec_bhh   = (const float*)d_in[18];
    const float* last_W    = (const float*)d_in[19];
    const float* last_b    = (const float*)d_in[20];
    const float* att_in_W  = (const float*)d_in[21];
    const float* att_in_b  = (const float*)d_in[22];
    const float* att_out_W = (const float*)d_in[23];
    const float* att_out_b = (const float*)d_in[24];
    float* out = (float*)d_out;

    static int smem_set = 0;
    int dec_smem = (int)sizeof(SAtt);
    if (dec_smem < (int)sizeof(SEpi)) dec_smem = (int)sizeof(SEpi);
    if (!smem_set) {
        cudaFuncSetAttribute(k_dec, cudaFuncAttributeMaxDynamicSharedMemorySize,
                             dec_smem);
        smem_set = 1;
    }

    k_transp<<<dim3(80, 3), 256>>>(enc_f_Wih, enc_b_Wih, att_in_W);
    k_tab<<<63, 512>>>(att_in_W, dec_Wih, L_tab);
    k_gi<<<dim3(S / 16, 2), 320>>>(x, E_tab, enc_f_bih, enc_f_bhh, enc_b_bih, enc_b_bhh);
    k_recur<<<2, 640>>>(enc_f_Whh, enc_b_Whh, enc_f_bhh, enc_b_bhh);
    k_kv<<<S / 16, 416>>>(att_in_b);
    k_sent<<<1, 512>>>(mid_W, mid_b, att_in_W, att_in_b, dec_Wih);
    k_dec<<<NATT + 1, 1024, dec_smem>>>(att_out_W, att_out_b, dec_Wih, dec_bih,
                                        dec_bhh, last_b, last_W, att_in_W, att_in_b,
                                        out);
}

// round 11
// speedup vs baseline: 1.3899x; 1.3899x over previous
#include <cuda_runtime.h>
#include <cstdint>

#define S 4096
#define MAXLEN 50
#define NATT 64

// ---------------- scratch ----------------
__device__ float g_G[2 * S * 300];
__device__ float g_WTenc[2 * 256 * 300];
__device__ float g_WAT[200 * 400];
__device__ float g_enc[S * 200];
__device__ float g_kp[S * 200];             // kp row-major [i][k]
__device__ float g_vp[S * 200];             // vp row-major [i][g]
__device__ float g_QL[1000 * 200];          // Wq[:,100:200] @ L_tab[i]
__device__ float g_GL[1000 * 300];          // dec_Wih[:,100:200] @ L_tab[i]
__device__ float g_gihd0[300];              // dec_Wih[:,100:200] @ sent  (t=0 path)
__device__ float g_q[200];
__device__ float g_hd[100];
__device__ float g_qpart[200];
__device__ int   g_idx;
__device__ float g_pm[NATT];
__device__ float g_pz[NATT];
__device__ float g_pv[NATT * 200];
__device__ float g_pamv[NATT];
__device__ int   g_pami[NATT];
__device__ unsigned g_cnt1[MAXLEN];
__device__ unsigned g_cnt2[MAXLEN];
__device__ unsigned g_hdflag[MAXLEN];
__device__ unsigned g_qpflag[MAXLEN];
__device__ unsigned g_qflag[MAXLEN + 1];

__device__ __forceinline__ float tanhapx(float x) {
    float y; asm("tanh.approx.f32 %0, %1;" : "=f"(y) : "f"(x)); return y;
}
__device__ __forceinline__ float sigapx(float x) {
    return 0.5f + 0.5f * tanhapx(0.5f * x);
}
__device__ __forceinline__ unsigned vld(const unsigned* p) {
    return *(volatile const unsigned*)p;
}
__device__ __forceinline__ float warp_sum(float a) {
#pragma unroll
    for (int o = 16; o; o >>= 1) a += __shfl_xor_sync(0xffffffffu, a, o);
    return a;
}
__device__ __forceinline__ float warp_max(float a) {
#pragma unroll
    for (int o = 16; o; o >>= 1) a = fmaxf(a, __shfl_xor_sync(0xffffffffu, a, o));
    return a;
}
__device__ __forceinline__ float red8(float a) {
    a += __shfl_xor_sync(0xffffffffu, a, 4);
    a += __shfl_xor_sync(0xffffffffu, a, 2);
    a += __shfl_xor_sync(0xffffffffu, a, 1);
    return a;
}

// ---------------- K_transp ----------------
__global__ void k_transp(const float* fWih, const float* bWih, const float* attW) {
    int region = blockIdx.y;
    const float* src; float* dst; int R, C;
    switch (region) {
        case 0: src = fWih;             dst = g_WTenc;          R = 300; C = 256; break;
        case 1: src = bWih;             dst = g_WTenc + 76800;  R = 300; C = 256; break;
        default: src = attW + 200*200;  dst = g_WAT;            R = 400; C = 200; break;
    }
    int total = R * C;
    for (int idx = blockIdx.x * blockDim.x + threadIdx.x; idx < total;
         idx += gridDim.x * blockDim.x) {
        int r = idx / C, c = idx % C;
        dst[c * R + r] = src[r * C + c];
    }
}

// ---------------- K_tab: QL/GL tables ----------------
__global__ void __launch_bounds__(512) k_tab(const float* attInW, const float* decWih,
                                             const float* L_tab) {
    __shared__ float Lt[16][100];
    int tid = threadIdx.x;
    int ib = blockIdx.x * 16;
    for (int i = tid; i < 16 * 100; i += 512) {
        int j = i / 100, k = i % 100;
        Lt[j][k] = (ib + j < 1000) ? L_tab[(ib + j) * 100 + k] : 0.f;
    }
    __syncthreads();
    if (tid < 500) {
        const float* wp = (tid < 200) ? (attInW + tid * 200 + 100)
                                      : (decWih + (tid - 200) * 400 + 100);
        float acc[16];
#pragma unroll
        for (int j = 0; j < 16; j++) acc[j] = 0.f;
        for (int k = 0; k < 100; k++) {
            float wv = wp[k];
#pragma unroll
            for (int j = 0; j < 16; j++) acc[j] += wv * Lt[j][k];
        }
        for (int j = 0; j < 16; j++) {
            if (ib + j < 1000) {
                if (tid < 200) g_QL[(ib + j) * 200 + tid] = acc[j];
                else           g_GL[(ib + j) * 300 + tid - 200] = acc[j];
            }
        }
    }
}

// ---------------- K0: gi precompute ----------------
__global__ void __launch_bounds__(320) k_gi(const int* x, const float* E_tab,
                                            const float* fbih, const float* fbhh,
                                            const float* bbih, const float* bbhh) {
    int dir = blockIdx.y;
    int t0 = blockIdx.x * 16;
    __shared__ int xi[16];
    __shared__ __align__(16) float emb_s[16 * 256];
    int tid = threadIdx.x;
    if (tid < 16) {
        int tg = dir ? (S - 1 - (t0 + tid)) : (t0 + tid);
        xi[tid] = x[tg];
    }
    __syncthreads();
    for (int i = tid; i < 16 * 256; i += 320) {
        int tt = i >> 8, k = i & 255;
        emb_s[i] = E_tab[(size_t)xi[tt] * 256 + k];
    }
    __syncthreads();
    if (tid < 300) {
        int g = tid;
        const float* bih = dir ? bbih : fbih;
        const float* bhh = dir ? bbhh : fbhh;
        float bias = bih[g] + (g < 200 ? bhh[g] : 0.f);
        float acc[16];
#pragma unroll
        for (int tt = 0; tt < 16; tt++) acc[tt] = bias;
        const float* WT = g_WTenc + dir * 256 * 300;
        for (int k4 = 0; k4 < 64; k4++) {
            float w0 = WT[(4 * k4 + 0) * 300 + g];
            float w1 = WT[(4 * k4 + 1) * 300 + g];
            float w2 = WT[(4 * k4 + 2) * 300 + g];
            float w3 = WT[(4 * k4 + 3) * 300 + g];
#pragma unroll
            for (int tt = 0; tt < 16; tt++) {
                float4 e = *reinterpret_cast<const float4*>(emb_s + tt * 256 + 4 * k4);
                acc[tt] += e.x * w0 + e.y * w1 + e.z * w2 + e.w * w3;
            }
        }
        float* Gd = g_G + (size_t)dir * S * 300;
#pragma unroll
        for (int tt = 0; tt < 16; tt++) Gd[(t0 + tt) * 300 + g] = acc[tt];
    }
}

// ---------------- K1: GRU recurrence (2 blocks: fwd / bwd) ----------------
// 640 threads. Dot threads: row = tid>>1, c = tid&1 (halves adjacent in warp,
// combined by one shfl_xor(1)); even lane writes part[row] (300 values).
// h halves at float-offsets 0 and 68 (both 16B-aligned, different bank groups).
// Epilogue (tid<100) reads 3 part values; h carried in a register.
__global__ void __launch_bounds__(640, 1) k_recur(const float* fWhh, const float* bWhh,
                                                  const float* fbhh, const float* bbhh) {
    int dir = blockIdx.x;
    const float* Whh = dir ? bWhh : fWhh;
    const float* bhh = dir ? bbhh : fbhh;
    const float* Gd = g_G + (size_t)dir * S * 300;
    __shared__ __align__(16) float h_s[136];   // [0..49]=h[0:50], [68..117]=h[50:100]
    __shared__ float part[304];
    __shared__ float bhn_s[100];
    int tid = threadIdx.x;
    int row = tid >> 1;                 // 0..319 (clamped below)
    if (row > 299) row = 299;
    int c = tid & 1;
    bool dotp = (tid < 608);            // lanes 600-607 participate (clamped row)
    bool wr_ok = (tid < 600) && (c == 0);

    unsigned long long w[25];
    if (dotp) {
        const unsigned long long* wp =
            reinterpret_cast<const unsigned long long*>(Whh + row * 100 + c * 50);
#pragma unroll
        for (int k = 0; k < 25; k++) w[k] = wp[k];
    }
    if (tid < 136) h_s[tid] = 0.f;
    if (tid < 100) bhn_s[tid] = bhh[200 + tid];
    float gr = 0.f, gz = 0.f, gn = 0.f, h_reg = 0.f;
    if (tid < 100) { gr = Gd[tid]; gz = Gd[100 + tid]; gn = Gd[200 + tid]; }
    __syncthreads();

    float* outbase = g_enc + (dir ? 100 : 0);
    for (int t = 0; t < S; t++) {
        float ngr = 0.f, ngz = 0.f, ngn = 0.f;
        if (tid < 100) {
            int tn = (t + 1 < S) ? (t + 1) : (S - 1);
            const float* Gn = Gd + tn * 300;
            ngr = Gn[tid]; ngz = Gn[100 + tid]; ngn = Gn[200 + tid];
        }
        if (dotp) {
            unsigned long long a0 = 0ULL, a1 = 0ULL, a2 = 0ULL, a3 = 0ULL;
            const float* hbuf = h_s + c * 68;
            const ulonglong2* hp = reinterpret_cast<const ulonglong2*>(hbuf);
#pragma unroll
            for (int j = 0; j < 6; j++) {
                ulonglong2 ha = hp[2 * j];
                ulonglong2 hb = hp[2 * j + 1];
                asm("fma.rn.f32x2 %0, %1, %2, %0;" : "+l"(a0) : "l"(w[4*j]),   "l"(ha.x));
                asm("fma.rn.f32x2 %0, %1, %2, %0;" : "+l"(a1) : "l"(w[4*j+1]), "l"(ha.y));
                asm("fma.rn.f32x2 %0, %1, %2, %0;" : "+l"(a2) : "l"(w[4*j+2]), "l"(hb.x));
                asm("fma.rn.f32x2 %0, %1, %2, %0;" : "+l"(a3) : "l"(w[4*j+3]), "l"(hb.y));
            }
            {
                unsigned long long hl =
                    *reinterpret_cast<const unsigned long long*>(hbuf + 48);
                asm("fma.rn.f32x2 %0, %1, %2, %0;" : "+l"(a0) : "l"(w[24]), "l"(hl));
            }
            asm("add.rn.f32x2 %0, %0, %1;" : "+l"(a0) : "l"(a2));
            asm("add.rn.f32x2 %0, %0, %1;" : "+l"(a1) : "l"(a3));
            asm("add.rn.f32x2 %0, %0, %1;" : "+l"(a0) : "l"(a1));
            float2 f = *reinterpret_cast<float2*>(&a0);
            float half = f.x + f.y;
            float full = half + __shfl_xor_sync(0xffffffffu, half, 1);
            if (wr_ok) part[row] = full;
        }
        __syncthreads();
        if (tid < 100) {
            float ar = gr + part[tid];
            float az = gz + part[100 + tid];
            float ah = part[200 + tid] + bhn_s[tid];
            float rg = sigapx(ar);
            float zg = sigapx(az);
            float ng = tanhapx(gn + rg * ah);
            float hn = ng + zg * (h_reg - ng);
            h_reg = hn;
            h_s[(tid < 50) ? tid : tid + 18] = hn;
            int trow = dir ? (S - 1 - t) : t;
            outbase[trow * 200 + tid] = hn;
            gr = ngr; gz = ngz; gn = ngn;
        }
        __syncthreads();
    }
}

// ---------------- K2: kp and vp (both row-major) ----------------
__global__ void __launch_bounds__(416) k_kv(const float* att_in_b) {
    int i0 = blockIdx.x * 16;
    __shared__ __align__(16) float enc_s[16 * 200];
    int tid = threadIdx.x;
    for (int i = tid; i < 3200; i += 416) enc_s[i] = g_enc[i0 * 200 + i];
    __syncthreads();
    if (tid < 400) {
        int g = tid;
        float bias = att_in_b[200 + g];
        float acc[16];
#pragma unroll
        for (int tt = 0; tt < 16; tt++) acc[tt] = bias;
        for (int k4 = 0; k4 < 50; k4++) {
            float w0 = g_WAT[(4 * k4 + 0) * 400 + g];
            float w1 = g_WAT[(4 * k4 + 1) * 400 + g];
            float w2 = g_WAT[(4 * k4 + 2) * 400 + g];
            float w3 = g_WAT[(4 * k4 + 3) * 400 + g];
#pragma unroll
            for (int tt = 0; tt < 16; tt++) {
                float4 e = *reinterpret_cast<const float4*>(enc_s + tt * 200 + 4 * k4);
                acc[tt] += e.x * w0 + e.y * w1 + e.z * w2 + e.w * w3;
            }
        }
        if (g < 200) {
#pragma unroll
            for (int tt = 0; tt < 16; tt++) g_kp[(i0 + tt) * 200 + g] = acc[tt];
        } else {
            int vg = g - 200;
#pragma unroll
            for (int tt = 0; tt < 16; tt++) g_vp[(i0 + tt) * 200 + vg] = acc[tt];
        }
    }
}

// ---------------- K3: sent, q0, gihd0, flag reset ----------------
__global__ void __launch_bounds__(512) k_sent(const float* mid_W, const float* mid_b,
                                              const float* att_in_W, const float* att_in_b,
                                              const float* decWih) {
    __shared__ float u[200];
    __shared__ float sent_s[100];
    int tid = threadIdx.x;
    for (int i = tid; i < MAXLEN; i += 512) {
        g_cnt1[i] = 0; g_cnt2[i] = 0; g_hdflag[i] = 0; g_qflag[i] = 0; g_qpflag[i] = 0;
    }
    if (tid == 0) g_qflag[MAXLEN] = 0;
    if (tid < 100) {
        u[tid] = g_enc[100 + tid];
        u[100 + tid] = g_enc[(S - 1) * 200 + tid];
    }
    __syncthreads();
    if (tid < 100) {
        float acc = mid_b[tid];
#pragma unroll 4
        for (int k = 0; k < 200; k++) acc += mid_W[tid * 200 + k] * u[k];
        sent_s[tid] = acc;
    }
    __syncthreads();
    if (tid < 200) {
        float acc = att_in_b[tid];
#pragma unroll 4
        for (int k = 0; k < 100; k++) acc += att_in_W[tid * 200 + 100 + k] * sent_s[k];
        g_q[tid] = acc;
    }
    if (tid < 300) {
        float acc = 0.f;
#pragma unroll 4
        for (int k = 0; k < 100; k++) acc += decWih[tid * 400 + 100 + k] * sent_s[k];
        g_gihd0[tid] = acc;
    }
}

// ---------------- fused persistent decoder ----------------
struct SAtt {
    float kp[64 * 200];   // [row][k]
    float vp[64 * 200];   // [i][g]
    float lw[16 * 100];
    float lb[16];
    float q[200];
    float s[64];
    float e[64];
    float hd[100];
    float pvp[4 * 200];
    float scp[16 * 4];
    float sc[16];
    float redM;
    int fin;
    int idxs;
};
struct SEpi {
    float pm[64], pz[64], coef[64];
    float part[4 * 200];
    float araw[200];
    float att_s[200];
    float gi[300];
    float gibias[300];
    float dhn[100];
    float bo[200], bq[200];
    float hd_s[100];
    float ghd_s[300];
    float redM, invZ;
};

__global__ void __launch_bounds__(1024, 1) k_dec(
    const float* attOutW, const float* attOutB,
    const float* decWih, const float* dec_bih, const float* dec_bhh,
    const float* lastB, const float* lastW,
    const float* attInW, const float* attInB, float* out) {
    extern __shared__ char sm_raw[];
    int tid = threadIdx.x;
    int b = blockIdx.x;
    int g8 = tid >> 3, s8 = tid & 7;

    if (b < NATT) {
        // ================= attention / scores block =================
        SAtt* sm = (SAtt*)sm_raw;
        int i0 = b * 64;
        for (int i = tid; i < 12800; i += 1024) sm->kp[i] = g_kp[i0 * 200 + i];
        for (int i = tid; i < 12800; i += 1024) sm->vp[i] = g_vp[i0 * 200 + i];
        int r0 = b * 16;
        int nrows = 1000 - r0; if (nrows > 16) nrows = 16; if (nrows < 0) nrows = 0;
        for (int i = tid; i < nrows * 100; i += 1024) sm->lw[i] = lastW[r0 * 100 + i];
        if (tid < nrows) sm->lb[tid] = lastB[r0 + tid];
        __syncthreads();
        const float SCALE = 0.07071067811865475f;  // 1/sqrt(200)
        int g16 = tid >> 4, s16 = tid & 15;

        for (int t = 0; t < MAXLEN; t++) {
            if (t > 0) {
                if (tid == 0) while (vld(&g_qflag[t]) == 0u) __nanosleep(20);
                __syncthreads();
            }
            if (tid < 200) sm->q[tid] = __ldcg(&g_q[tid]);
            __syncthreads();
            // s = kp @ q : 16 lanes per row
            if (g16 < 64) {
                float acc = 0.f;
#pragma unroll
                for (int jx = 0; jx < 13; jx++) {
                    int k = s16 + 16 * jx;
                    if (k < 200) acc += sm->kp[g16 * 200 + k] * sm->q[k];
                }
                acc += __shfl_xor_sync(0xffffffffu, acc, 8);
                acc = red8(acc);
                if (s16 == 0) sm->s[g16] = acc * SCALE;
            }
            __syncthreads();
            if (tid < 32) {
                float m = warp_max(fmaxf(sm->s[tid], sm->s[tid + 32]));
                if (tid == 0) sm->redM = m;
            }
            __syncthreads();
            if (tid < 64) sm->e[tid] = __expf(sm->s[tid] - sm->redM);
            __syncthreads();
            if (tid < 32) {
                float z = warp_sum(sm->e[tid] + sm->e[tid + 32]);
                if (tid == 0) { __stcg(&g_pm[b], sm->redM); __stcg(&g_pz[b], z); }
            }
            if (tid < 800) {
                int g = tid % 200, ip = tid / 200;
                float a = 0.f;
#pragma unroll
                for (int jx = 0; jx < 16; jx++) {
                    int i2 = ip * 16 + jx;
                    a += sm->e[i2] * sm->vp[i2 * 200 + g];
                }
                sm->pvp[ip * 200 + g] = a;
            }
            __syncthreads();
            if (tid < 200) {
                float a = sm->pvp[tid] + sm->pvp[200 + tid] + sm->pvp[400 + tid] +
                          sm->pvp[600 + tid];
                __stcg(&g_pv[b * 200 + tid], a);
            }
            __threadfence();
            __syncthreads();
            if (tid == 0) atomicAdd(&g_cnt1[t], 1u);

            // wait for hd from epilogue
            if (tid == 0) while (vld(&g_hdflag[t]) == 0u) __nanosleep(20);
            __syncthreads();
            if (tid < 100) sm->hd[tid] = __ldcg(&g_hd[tid]);
            __syncthreads();
            if (tid < nrows * 4) {
                int row = tid >> 2, kp4 = tid & 3;
                float a = 0.f;
#pragma unroll
                for (int kk = 0; kk < 25; kk++)
                    a += sm->lw[row * 100 + kp4 * 25 + kk] * sm->hd[kp4 * 25 + kk];
                sm->scp[tid] = a;
            }
            __syncthreads();
            if (tid < nrows) {
                float sc = sm->scp[tid * 4] + sm->scp[tid * 4 + 1] +
                           sm->scp[tid * 4 + 2] + sm->scp[tid * 4 + 3] + sm->lb[tid];
                sm->sc[tid] = sc;
                out[t * 1000 + r0 + tid] = sc;
            }
            __syncthreads();
            if (tid == 0) {
                float bv = -3.4e38f; int bi = 0x7fffffff;
                for (int rr = 0; rr < nrows; rr++)
                    if (sm->sc[rr] > bv) { bv = sm->sc[rr]; bi = r0 + rr; }
                __stcg(&g_pamv[b], bv);
                __stcg(&g_pami[b], bi);
                __threadfence();
                unsigned old = atomicAdd(&g_cnt2[t], 1u);
                sm->fin = (old == NATT - 1) ? 1 : 0;
            }
            __syncthreads();
            if (sm->fin) {
                // last block: global argmax + q finalize
                if (tid < 32) {
                    float v1 = __ldcg(&g_pamv[tid]), v2 = __ldcg(&g_pamv[tid + 32]);
                    int i1 = __ldcg(&g_pami[tid]), i2 = __ldcg(&g_pami[tid + 32]);
                    float bv; int bi;
                    if (v1 > v2 || (v1 == v2 && i1 < i2)) { bv = v1; bi = i1; }
                    else { bv = v2; bi = i2; }
#pragma unroll
                    for (int o = 16; o; o >>= 1) {
                        float ov = __shfl_xor_sync(0xffffffffu, bv, o);
                        int oi = __shfl_xor_sync(0xffffffffu, bi, o);
                        if (ov > bv || (ov == bv && oi < bi)) { bv = ov; bi = oi; }
                    }
                    if (tid == 0) sm->idxs = bi;
                }
                if (tid == 0) while (vld(&g_qpflag[t]) == 0u) __nanosleep(20);
                __syncthreads();
                int idx = sm->idxs;
                if (tid < 200)
                    __stcg(&g_q[tid], __ldcg(&g_qpart[tid]) + g_QL[idx * 200 + tid]);
                if (tid == 0) *(volatile int*)&g_idx = idx;
                __threadfence();
                __syncthreads();
                if (tid == 0) *(volatile unsigned*)&g_qflag[t + 1] = 1u;
            }
            __syncthreads();
        }
    } else {
        // ================= epilogue block =================
        SEpi* sm = (SEpi*)sm_raw;
        for (int i = tid; i < 300; i += 1024)
            sm->gibias[i] = dec_bih[i] + (i < 200 ? dec_bhh[i] : 0.f);
        for (int i = tid; i < 100; i += 1024) sm->dhn[i] = dec_bhh[200 + i];
        for (int i = tid; i < 200; i += 1024) {
            sm->bo[i] = attOutB[i];
            sm->bq[i] = attInB[i];
        }
        __syncthreads();

        for (int t = 0; t < MAXLEN; t++) {
            if (tid == 0) while (vld(&g_cnt1[t]) < NATT) __nanosleep(20);
            __syncthreads();
            // prefetch GL contribution (idx-dependent) while softmax/attproj run
            float glv = 0.f;
            if (tid < 300) {
                if (t == 0) glv = g_gihd0[tid];
                else {
                    int idx = *(volatile int*)&g_idx;
                    glv = __ldcg(&g_GL[idx * 300 + tid]);
                }
            }
            if (tid < 64) sm->pm[tid] = __ldcg(&g_pm[tid]);
            else if (tid < 128) sm->pz[tid - 64] = __ldcg(&g_pz[tid - 64]);
            __syncthreads();
            if (tid < 32) {
                float m = warp_max(fmaxf(sm->pm[tid], sm->pm[tid + 32]));
                if (tid == 0) sm->redM = m;
            }
            __syncthreads();
            if (tid < 64) sm->coef[tid] = __expf(sm->pm[tid] - sm->redM);
            __syncthreads();
            if (tid < 32) {
                float z = warp_sum(sm->coef[tid] * sm->pz[tid] +
                                   sm->coef[tid + 32] * sm->pz[tid + 32]);
                if (tid == 0) sm->invZ = __fdividef(1.f, z);
            }
            __syncthreads();
            if (tid < 800) {
                int g = tid % 200, ip = tid / 200;
                float a = 0.f;
#pragma unroll
                for (int jx = 0; jx < 16; jx++) {
                    int bb = ip * 16 + jx;
                    a += sm->coef[bb] * __ldcg(&g_pv[bb * 200 + g]);
                }
                sm->part[ip * 200 + g] = a;
            }
            __syncthreads();
            if (tid < 200)
                sm->araw[tid] = (sm->part[tid] + sm->part[200 + tid] +
                                 sm->part[400 + tid] + sm->part[600 + tid]) * sm->invZ;
            __syncthreads();
            // att projection: 8 lanes per row
            for (int r = g8; r < 200; r += 128) {
                float a = 0.f;
#pragma unroll
                for (int jx = 0; jx < 25; jx++) {
                    int k = s8 + 8 * jx;
                    a += attOutW[r * 200 + k] * sm->araw[k];
                }
                a = red8(a);
                if (s8 == 0) sm->att_s[r] = a + sm->bo[r];
            }
            __syncthreads();
            // gi (att part): 8 lanes per row over dec_Wih[:, 200:400]
            for (int r = g8; r < 300; r += 128) {
                float a = 0.f;
#pragma unroll
                for (int jx = 0; jx < 25; jx++) {
                    int k = s8 + 8 * jx;
                    a += decWih[r * 400 + 200 + k] * sm->att_s[k];
                }
                a = red8(a);
                if (s8 == 0) sm->gi[r] = a;
            }
            __syncthreads();
            if (tid < 300) {
                float base = sm->gi[tid] + glv + sm->gibias[tid];
                if (t > 0) base += sm->ghd_s[tid];
                sm->gi[tid] = base;
            }
            __syncthreads();
            if (tid < 100) {
                float r_ = sigapx(sm->gi[tid]);
                float z_ = sigapx(sm->gi[100 + tid]);
                float n_ = tanhapx(sm->gi[200 + tid] + r_ * sm->dhn[tid]);
                float hd = (1.f - z_) * n_;
                sm->hd_s[tid] = hd;
                __stcg(&g_hd[tid], hd);
            }
            __threadfence();
            __syncthreads();
            if (tid == 0) *(volatile unsigned*)&g_hdflag[t] = 1u;

            // overlap with att scores: ghd_pre (next step) + qpart (finalizer)
            for (int rr = g8; rr < 500; rr += 128) {
                float a = 0.f;
                if (rr < 300) {
#pragma unroll
                    for (int jx = 0; jx < 13; jx++) {
                        int k = s8 + 8 * jx;
                        if (k < 100) a += decWih[rr * 400 + k] * sm->hd_s[k];
                    }
                } else {
#pragma unroll
                    for (int jx = 0; jx < 13; jx++) {
                        int k = s8 + 8 * jx;
                        if (k < 100) a += attInW[(rr - 300) * 200 + k] * sm->hd_s[k];
                    }
                }
                a = red8(a);
                if (s8 == 0) {
                    if (rr < 300) sm->ghd_s[rr] = a;
                    else __stcg(&g_qpart[rr - 300], a + sm->bq[rr - 300]);
                }
            }
            __threadfence();
            __syncthreads();
            if (tid == 0) *(volatile unsigned*)&g_qpflag[t] = 1u;
        }
    }
}

// ---------------- host launcher ----------------
extern "C" void kernel_launch(void* const* d_in, const int* in_sizes, int n_in,
                              void* d_out, int out_size) {
    const int*   x         = (const int*)  d_in[0];
    const float* E_tab     = (const float*)d_in[1];
    const float* L_tab     = (const float*)d_in[2];
    const float* enc_f_Wih = (const float*)d_in[3];
    const float* enc_f_Whh = (const float*)d_in[4];
    const float* enc_f_bih = (const float*)d_in[5];
    const float* enc_f_bhh = (const float*)d_in[6];
    const float* enc_b_Wih = (const float*)d_in[7];
    const float* enc_b_Whh = (const float*)d_in[8];
    const float* enc_b_bih = (const float*)d_in[9];
    const float* enc_b_bhh = (const float*)d_in[10];
    const float* mid_W     = (const float*)d_in[11];
    const float* mid_b     = (const float*)d_in[12];
    const float* dec_Wih   = (const float*)d_in[15];
    const float* dec_bih   = (const float*)d_in[17];
    const float* dec_bhh   = (const float*)d_in[18];
    const float* last_W    = (const float*)d_in[19];
    const float* last_b    = (const float*)d_in[20];
    const float* att_in_W  = (const float*)d_in[21];
    const float* att_in_b  = (const float*)d_in[22];
    const float* att_out_W = (const float*)d_in[23];
    const float* att_out_b = (const float*)d_in[24];
    float* out = (float*)d_out;

    static int smem_set = 0;
    int dec_smem = (int)sizeof(SAtt);
    if (dec_smem < (int)sizeof(SEpi)) dec_smem = (int)sizeof(SEpi);
    if (!smem_set) {
        cudaFuncSetAttribute(k_dec, cudaFuncAttributeMaxDynamicSharedMemorySize,
                             dec_smem);
        smem_set = 1;
    }

    k_transp<<<dim3(80, 3), 256>>>(enc_f_Wih, enc_b_Wih, att_in_W);
    k_tab<<<63, 512>>>(att_in_W, dec_Wih, L_tab);
    k_gi<<<dim3(S / 16, 2), 320>>>(x, E_tab, enc_f_bih, enc_f_bhh, enc_b_bih, enc_b_bhh);
    k_recur<<<2, 640>>>(enc_f_Whh, enc_b_Whh, enc_f_bhh, enc_b_bhh);
    k_kv<<<S / 16, 416>>>(att_in_b);
    k_sent<<<1, 512>>>(mid_W, mid_b, att_in_W, att_in_b, dec_Wih);
    k_dec<<<NATT + 1, 1024, dec_smem>>>(att_out_W, att_out_b, dec_Wih, dec_bih,
                                        dec_bhh, last_b, last_W, att_in_W, att_in_b,
                                        out);
}